// round 8
// baseline (speedup 1.0000x reference)
#include <cuda_runtime.h>
#include <cstdint>
#include <cstddef>
#include <cfloat>

// Problem shape
#define BB   8
#define T1C  2048
#define T2C  2048
#define DD   256

// Work decomposition: 2048 units = 8 b x 16 i-tiles(128) x 16 j-tiles(128)
#define UNITS  2048
#define NCTA   148

// smem layout
#define BMP  132                      // A row pad (floats)
#define BNU  129                      // B row stride (u64, odd -> 2-way STS only)
#define SM_BS (256 * BMP * 4)         // 135168
#define SMEM_TOTAL (SM_BS + 2 * 32 * BNU * 8)   // 135168 + 66048 = 201216

typedef unsigned long long ull;

__device__ ull g_best[BB * T1C];      // (enc(score)<<32) | (2047-j)

// ---------------------------------------------------------------------------
static __device__ __forceinline__ ull pk2(float lo, float hi) {
    ull r;
    asm("mov.b64 %0, {%1, %2};" : "=l"(r) : "f"(lo), "f"(hi));
    return r;
}
static __device__ __forceinline__ ull fma2(ull a, ull b, ull c) {
    ull d;
    asm("fma.rn.f32x2 %0, %1, %2, %3;" : "=l"(d) : "l"(a), "l"(b), "l"(c));
    return d;
}
static __device__ __forceinline__ void upk2(ull v, float& lo, float& hi) {
    asm("mov.b64 {%0, %1}, %2;" : "=f"(lo), "=f"(hi) : "l"(v));
}
// order-preserving float->uint encoding
static __device__ __forceinline__ unsigned enc(float x) {
    unsigned u = __float_as_uint(x);
    return (u & 0x80000000u) ? ~u : (u | 0x80000000u);
}

// ---------------------------------------------------------------------------
// init: reset the per-row best records (graph-replay safe)
// ---------------------------------------------------------------------------
__global__ void __launch_bounds__(512)
init_best_kernel()
{
    g_best[blockIdx.x * 512 + threadIdx.x] = 0ull;   // < enc of any real score
}

// ---------------------------------------------------------------------------
// Persistent fp32 GEMM + argmax. 148 CTAs x 512 threads, 1 CTA/SM.
// Per unit: full-K (256) dot of a 128x128 (i,j) tile; FFMA2 packed over
// i-pairs; B operands pre-duplicated as (b,b) u64 in smem so the inner loop
// is loads + FFMA2 only. Microtile: 8 i (4 u64 pairs) x 4 j per thread,
// j strided by 32 so B loads are conflict-free LDS.64.
// ---------------------------------------------------------------------------
__global__ void __launch_bounds__(512, 1)
gemm_argmax_kernel(const float* __restrict__ s1, const float* __restrict__ s2,
                   float* __restrict__ out)
{
    extern __shared__ __align__(16) char smem[];
    float* As = (float*)smem;                       // As[k][i], k-major
    ull*   Bs = (ull*)(smem + SM_BS);               // Bs[2][32][BNU] dup pairs

    const int tid  = threadIdx.x;
    const int wid  = tid >> 5, lane = tid & 31;
    const int c    = blockIdx.x;

    // ---- zero the one-hot output region (replaces cudaMemset; overlaps)
    {
        const float4 z = make_float4(0.f, 0.f, 0.f, 0.f);
        float4* oz = (float4*)(out + (size_t)BB * T1C * DD);
        const size_t tot = (size_t)BB * T1C * T2C / 4;
        for (size_t p = (size_t)c * 512 + tid; p < tot; p += (size_t)NCTA * 512)
            oz[p] = z;
    }

    const int u0 = (c * UNITS) / NCTA;
    const int u1 = ((c + 1) * UNITS) / NCTA;
    int curA = -1;

    #pragma unroll 1
    for (int u = u0; u < u1; u++) {
        const int b  = u >> 8;
        const int it = (u >> 4) & 15;
        const int jt = u & 15;
        const int i0 = it * 128, j0 = jt * 128;
        const float* s1b = s1 + ((size_t)(b << 11) + i0) * DD;
        const float* s2b = s2 + ((size_t)(b << 11) + j0) * DD;

        // ---- (re)stage A tile when (b, i-tile) changes (~2x per CTA)
        if ((u >> 4) != curA) {
            curA = u >> 4;
            __syncthreads();              // prior unit's As readers done
            #pragma unroll
            for (int r = 0; r < 16; r++) {
                int f = tid + 512 * r;
                int i = f >> 6, kq = f & 63;
                float4 v = ((const float4*)s1b)[(size_t)i * 64 + kq];
                int k = kq * 4;
                As[(k + 0) * BMP + i] = v.x;
                As[(k + 1) * BMP + i] = v.y;
                As[(k + 2) * BMP + i] = v.z;
                As[(k + 3) * BMP + i] = v.w;
            }
        }

        // ---- stage B chunk 0 (k 0..31) into buffer 0, duplicated pairs
        float4 rB[2];
        #pragma unroll
        for (int r = 0; r < 2; r++) {
            int f = tid + 512 * r;
            int j = f >> 3, kq = f & 7;
            rB[r] = ((const float4*)(s2b + (size_t)j * DD))[kq];
        }
        #pragma unroll
        for (int r = 0; r < 2; r++) {
            int f = tid + 512 * r;
            int j = f >> 3, k = (f & 7) * 4;
            Bs[(k + 0) * BNU + j] = pk2(rB[r].x, rB[r].x);
            Bs[(k + 1) * BNU + j] = pk2(rB[r].y, rB[r].y);
            Bs[(k + 2) * BNU + j] = pk2(rB[r].z, rB[r].z);
            Bs[(k + 3) * BNU + j] = pk2(rB[r].w, rB[r].w);
        }

        ull acc[4][4];
        #pragma unroll
        for (int p = 0; p < 4; p++)
            #pragma unroll
            for (int q = 0; q < 4; q++) acc[p][q] = 0ull;

        #pragma unroll 1
        for (int kc = 0; kc < 8; kc++) {
            __syncthreads();              // staged stores visible
            const int buf = kc & 1;

            if (kc < 7) {                 // prefetch next chunk from global
                const int kbase = (kc + 1) * 8;
                #pragma unroll
                for (int r = 0; r < 2; r++) {
                    int f = tid + 512 * r;
                    int j = f >> 3, kq = f & 7;
                    rB[r] = ((const float4*)(s2b + (size_t)j * DD))[kbase + kq];
                }
            }

            const float* Ab = As + (size_t)kc * 32 * BMP + wid * 8;
            const ull*   Bb = Bs + (size_t)buf * 32 * BNU + lane;
            #pragma unroll
            for (int kk = 0; kk < 32; kk++) {
                ulonglong2 a01 = *(const ulonglong2*)(Ab + kk * BMP);
                ulonglong2 a23 = *(const ulonglong2*)(Ab + kk * BMP + 4);
                ull b0 = Bb[kk * BNU];
                ull b1 = Bb[kk * BNU + 32];
                ull b2 = Bb[kk * BNU + 64];
                ull b3 = Bb[kk * BNU + 96];
                acc[0][0] = fma2(a01.x, b0, acc[0][0]);
                acc[1][0] = fma2(a01.y, b0, acc[1][0]);
                acc[2][0] = fma2(a23.x, b0, acc[2][0]);
                acc[3][0] = fma2(a23.y, b0, acc[3][0]);
                acc[0][1] = fma2(a01.x, b1, acc[0][1]);
                acc[1][1] = fma2(a01.y, b1, acc[1][1]);
                acc[2][1] = fma2(a23.x, b1, acc[2][1]);
                acc[3][1] = fma2(a23.y, b1, acc[3][1]);
                acc[0][2] = fma2(a01.x, b2, acc[0][2]);
                acc[1][2] = fma2(a01.y, b2, acc[1][2]);
                acc[2][2] = fma2(a23.x, b2, acc[2][2]);
                acc[3][2] = fma2(a23.y, b2, acc[3][2]);
                acc[0][3] = fma2(a01.x, b3, acc[0][3]);
                acc[1][3] = fma2(a01.y, b3, acc[1][3]);
                acc[2][3] = fma2(a23.x, b3, acc[2][3]);
                acc[3][3] = fma2(a23.y, b3, acc[3][3]);
            }

            // store prefetched chunk into the other buffer; its previous
            // readers finished before this iteration's top barrier, and its
            // next readers wait on the next iteration's top barrier.
            if (kc < 7) {
                ull* dst = Bs + (size_t)(buf ^ 1) * 32 * BNU;
                #pragma unroll
                for (int r = 0; r < 2; r++) {
                    int f = tid + 512 * r;
                    int j = f >> 3, k = (f & 7) * 4;
                    dst[(k + 0) * BNU + j] = pk2(rB[r].x, rB[r].x);
                    dst[(k + 1) * BNU + j] = pk2(rB[r].y, rB[r].y);
                    dst[(k + 2) * BNU + j] = pk2(rB[r].z, rB[r].z);
                    dst[(k + 3) * BNU + j] = pk2(rB[r].w, rB[r].w);
                }
            }
        }

        // ---- per-unit argmax fold: warp reduce, then one global atomic/row.
        // Thread's j values are j0 + lane + q*32: ascending in q, so strict
        // '>' keeps the smallest j within the thread; the packed u64 compare
        // (2047-j in low bits) breaks exact score ties toward smaller j
        // across threads/CTAs = numpy's first-max rule.
        #pragma unroll
        for (int p = 0; p < 4; p++) {
            float v0 = -FLT_MAX, v1 = -FLT_MAX;
            int   jA = 0, jB = 0;
            #pragma unroll
            for (int q = 0; q < 4; q++) {
                float lo, hi;
                upk2(acc[p][q], lo, hi);
                int jg = j0 + q * 32 + lane;
                if (lo > v0) { v0 = lo; jA = jg; }
                if (hi > v1) { v1 = hi; jB = jg; }
            }
            ull pk0 = ((ull)enc(v0) << 32) | (unsigned)(2047 - jA);
            ull pk1 = ((ull)enc(v1) << 32) | (unsigned)(2047 - jB);
            #pragma unroll
            for (int off = 16; off; off >>= 1) {
                ull o0 = __shfl_xor_sync(0xffffffffu, pk0, off);
                ull o1 = __shfl_xor_sync(0xffffffffu, pk1, off);
                if (o0 > pk0) pk0 = o0;
                if (o1 > pk1) pk1 = o1;
            }
            if (lane == 0) {
                const int row = (b << 11) + i0 + wid * 8 + 2 * p;
                atomicMax(&g_best[row], pk0);
                atomicMax(&g_best[row + 1], pk1);
            }
        }
    }
}

// ---------------------------------------------------------------------------
// gather + one-hot write (one warp per output row)
// ---------------------------------------------------------------------------
__global__ void __launch_bounds__(256)
gather_onehot_kernel(const float* __restrict__ s2, float* __restrict__ out)
{
    const int w    = threadIdx.x >> 5;
    const int lane = threadIdx.x & 31;
    const int r    = blockIdx.x * 8 + w;     // 0 .. BB*T1C-1
    const int b    = r >> 11;
    const int i    = r & (T1C - 1);
    const int j    = 2047 - (int)(unsigned)(g_best[r] & 0xFFFFFFFFull);

    const float4* src = (const float4*)(s2 + ((size_t)b * T2C + (size_t)j) * DD);
    float4*       dst = (float4*)(out + (size_t)r * DD);
    dst[lane]      = src[lane];
    dst[lane + 32] = src[lane + 32];

    if (lane == 0)
        out[(size_t)BB * T1C * DD + (size_t)b * T1C * T2C +
            (size_t)i * T2C + j] = 1.0f;
}

// ---------------------------------------------------------------------------
// host
// ---------------------------------------------------------------------------
extern "C" void kernel_launch(void* const* d_in, const int* in_sizes, int n_in,
                              void* d_out, int out_size)
{
    (void)in_sizes; (void)n_in; (void)out_size;
    const float* s1 = (const float*)d_in[0];
    const float* s2 = (const float*)d_in[1];
    float* out = (float*)d_out;

    init_best_kernel<<<(BB * T1C) / 512, 512>>>();

    cudaFuncSetAttribute(gemm_argmax_kernel,
                         cudaFuncAttributeMaxDynamicSharedMemorySize,
                         SMEM_TOTAL);
    gemm_argmax_kernel<<<NCTA, 512, SMEM_TOTAL>>>(s1, s2, out);

    gather_onehot_kernel<<<(BB * T1C) / 8, 256>>>(s2, out);
}

// round 9
// speedup vs baseline: 1.0006x; 1.0006x over previous
#include <cuda_runtime.h>
#include <cstdint>
#include <cstddef>
#include <cfloat>

// Problem shape
#define BB   8
#define T1C  2048
#define T2C  2048
#define DD   256

// Work decomposition: 2048 units = 8 b x 16 i-tiles(128) x 16 j-tiles(128)
#define UNITS  2048
#define NCTA   148

// smem layout
#define BMP  132                      // A row pad (floats)
#define BNU  129                      // B row stride (u64, odd -> 2-way STS only)
#define SM_BS (256 * BMP * 4)         // 135168
#define SMEM_TOTAL (SM_BS + 2 * 32 * BNU * 8)   // 135168 + 66048 = 201216

typedef unsigned long long ull;

__device__ ull g_best[BB * T1C];      // (enc(score)<<32) | (2047-j)

// ---------------------------------------------------------------------------
static __device__ __forceinline__ ull pk2(float lo, float hi) {
    ull r;
    asm("mov.b64 %0, {%1, %2};" : "=l"(r) : "f"(lo), "f"(hi));
    return r;
}
static __device__ __forceinline__ ull fma2(ull a, ull b, ull c) {
    ull d;
    asm("fma.rn.f32x2 %0, %1, %2, %3;" : "=l"(d) : "l"(a), "l"(b), "l"(c));
    return d;
}
static __device__ __forceinline__ void upk2(ull v, float& lo, float& hi) {
    asm("mov.b64 {%0, %1}, %2;" : "=f"(lo), "=f"(hi) : "l"(v));
}
// order-preserving float->uint encoding
static __device__ __forceinline__ unsigned enc(float x) {
    unsigned u = __float_as_uint(x);
    return (u & 0x80000000u) ? ~u : (u | 0x80000000u);
}

// ---------------------------------------------------------------------------
// init: reset the per-row best records (graph-replay safe)
// ---------------------------------------------------------------------------
__global__ void __launch_bounds__(512)
init_best_kernel()
{
    g_best[blockIdx.x * 512 + threadIdx.x] = 0ull;   // < enc of any real score
}

// ---------------------------------------------------------------------------
// Persistent fp32 GEMM + argmax. 148 CTAs x 512 threads, 1 CTA/SM.
// Per unit: full-K (256) dot of a 128x128 (i,j) tile; FFMA2 packed over
// i-pairs; B operands pre-duplicated as (b,b) u64 in smem so the inner loop
// is loads + FFMA2 only. Microtile: 8 i (4 u64 pairs) x 4 j per thread,
// j strided by 32 so B loads are conflict-free LDS.64.
// ---------------------------------------------------------------------------
__global__ void __launch_bounds__(512, 1)
gemm_argmax_kernel(const float* __restrict__ s1, const float* __restrict__ s2,
                   float* __restrict__ out)
{
    extern __shared__ __align__(16) char smem[];
    float* As = (float*)smem;                       // As[k][i], k-major
    ull*   Bs = (ull*)(smem + SM_BS);               // Bs[2][32][BNU] dup pairs

    const int tid  = threadIdx.x;
    const int wid  = tid >> 5, lane = tid & 31;
    const int c    = blockIdx.x;

    // ---- zero the one-hot output region (replaces cudaMemset; overlaps)
    {
        const float4 z = make_float4(0.f, 0.f, 0.f, 0.f);
        float4* oz = (float4*)(out + (size_t)BB * T1C * DD);
        const size_t tot = (size_t)BB * T1C * T2C / 4;
        for (size_t p = (size_t)c * 512 + tid; p < tot; p += (size_t)NCTA * 512)
            oz[p] = z;
    }

    const int u0 = (c * UNITS) / NCTA;
    const int u1 = ((c + 1) * UNITS) / NCTA;
    int curA = -1;

    #pragma unroll 1
    for (int u = u0; u < u1; u++) {
        const int b  = u >> 8;
        const int it = (u >> 4) & 15;
        const int jt = u & 15;
        const int i0 = it * 128, j0 = jt * 128;
        const float* s1b = s1 + ((size_t)(b << 11) + i0) * DD;
        const float* s2b = s2 + ((size_t)(b << 11) + j0) * DD;

        // ---- (re)stage A tile when (b, i-tile) changes (~2x per CTA)
        if ((u >> 4) != curA) {
            curA = u >> 4;
            __syncthreads();              // prior unit's As readers done
            #pragma unroll
            for (int r = 0; r < 16; r++) {
                int f = tid + 512 * r;
                int i = f >> 6, kq = f & 63;
                float4 v = ((const float4*)s1b)[(size_t)i * 64 + kq];
                int k = kq * 4;
                As[(k + 0) * BMP + i] = v.x;
                As[(k + 1) * BMP + i] = v.y;
                As[(k + 2) * BMP + i] = v.z;
                As[(k + 3) * BMP + i] = v.w;
            }
        }

        // ---- stage B chunk 0 (k 0..31) into buffer 0, duplicated pairs
        float4 rB[2];
        #pragma unroll
        for (int r = 0; r < 2; r++) {
            int f = tid + 512 * r;
            int j = f >> 3, kq = f & 7;
            rB[r] = ((const float4*)(s2b + (size_t)j * DD))[kq];
        }
        #pragma unroll
        for (int r = 0; r < 2; r++) {
            int f = tid + 512 * r;
            int j = f >> 3, k = (f & 7) * 4;
            Bs[(k + 0) * BNU + j] = pk2(rB[r].x, rB[r].x);
            Bs[(k + 1) * BNU + j] = pk2(rB[r].y, rB[r].y);
            Bs[(k + 2) * BNU + j] = pk2(rB[r].z, rB[r].z);
            Bs[(k + 3) * BNU + j] = pk2(rB[r].w, rB[r].w);
        }

        ull acc[4][4];
        #pragma unroll
        for (int p = 0; p < 4; p++)
            #pragma unroll
            for (int q = 0; q < 4; q++) acc[p][q] = 0ull;

        #pragma unroll 1
        for (int kc = 0; kc < 8; kc++) {
            __syncthreads();              // staged stores visible
            const int buf = kc & 1;

            if (kc < 7) {                 // prefetch next chunk from global
                const int kbase = (kc + 1) * 8;
                #pragma unroll
                for (int r = 0; r < 2; r++) {
                    int f = tid + 512 * r;
                    int j = f >> 3, kq = f & 7;
                    rB[r] = ((const float4*)(s2b + (size_t)j * DD))[kbase + kq];
                }
            }

            const float* Ab = As + (size_t)kc * 32 * BMP + wid * 8;
            const ull*   Bb = Bs + (size_t)buf * 32 * BNU + lane;
            #pragma unroll
            for (int kk = 0; kk < 32; kk++) {
                ulonglong2 a01 = *(const ulonglong2*)(Ab + kk * BMP);
                ulonglong2 a23 = *(const ulonglong2*)(Ab + kk * BMP + 4);
                ull b0 = Bb[kk * BNU];
                ull b1 = Bb[kk * BNU + 32];
                ull b2 = Bb[kk * BNU + 64];
                ull b3 = Bb[kk * BNU + 96];
                acc[0][0] = fma2(a01.x, b0, acc[0][0]);
                acc[1][0] = fma2(a01.y, b0, acc[1][0]);
                acc[2][0] = fma2(a23.x, b0, acc[2][0]);
                acc[3][0] = fma2(a23.y, b0, acc[3][0]);
                acc[0][1] = fma2(a01.x, b1, acc[0][1]);
                acc[1][1] = fma2(a01.y, b1, acc[1][1]);
                acc[2][1] = fma2(a23.x, b1, acc[2][1]);
                acc[3][1] = fma2(a23.y, b1, acc[3][1]);
                acc[0][2] = fma2(a01.x, b2, acc[0][2]);
                acc[1][2] = fma2(a01.y, b2, acc[1][2]);
                acc[2][2] = fma2(a23.x, b2, acc[2][2]);
                acc[3][2] = fma2(a23.y, b2, acc[3][2]);
                acc[0][3] = fma2(a01.x, b3, acc[0][3]);
                acc[1][3] = fma2(a01.y, b3, acc[1][3]);
                acc[2][3] = fma2(a23.x, b3, acc[2][3]);
                acc[3][3] = fma2(a23.y, b3, acc[3][3]);
            }

            // store prefetched chunk into the other buffer; its previous
            // readers finished before this iteration's top barrier, and its
            // next readers wait on the next iteration's top barrier.
            if (kc < 7) {
                ull* dst = Bs + (size_t)(buf ^ 1) * 32 * BNU;
                #pragma unroll
                for (int r = 0; r < 2; r++) {
                    int f = tid + 512 * r;
                    int j = f >> 3, k = (f & 7) * 4;
                    dst[(k + 0) * BNU + j] = pk2(rB[r].x, rB[r].x);
                    dst[(k + 1) * BNU + j] = pk2(rB[r].y, rB[r].y);
                    dst[(k + 2) * BNU + j] = pk2(rB[r].z, rB[r].z);
                    dst[(k + 3) * BNU + j] = pk2(rB[r].w, rB[r].w);
                }
            }
        }

        // ---- per-unit argmax fold: warp reduce, then one global atomic/row.
        // Thread's j values are j0 + lane + q*32: ascending in q, so strict
        // '>' keeps the smallest j within the thread; the packed u64 compare
        // (2047-j in low bits) breaks exact score ties toward smaller j
        // across threads/CTAs = numpy's first-max rule.
        #pragma unroll
        for (int p = 0; p < 4; p++) {
            float v0 = -FLT_MAX, v1 = -FLT_MAX;
            int   jA = 0, jB = 0;
            #pragma unroll
            for (int q = 0; q < 4; q++) {
                float lo, hi;
                upk2(acc[p][q], lo, hi);
                int jg = j0 + q * 32 + lane;
                if (lo > v0) { v0 = lo; jA = jg; }
                if (hi > v1) { v1 = hi; jB = jg; }
            }
            ull pk0 = ((ull)enc(v0) << 32) | (unsigned)(2047 - jA);
            ull pk1 = ((ull)enc(v1) << 32) | (unsigned)(2047 - jB);
            #pragma unroll
            for (int off = 16; off; off >>= 1) {
                ull o0 = __shfl_xor_sync(0xffffffffu, pk0, off);
                ull o1 = __shfl_xor_sync(0xffffffffu, pk1, off);
                if (o0 > pk0) pk0 = o0;
                if (o1 > pk1) pk1 = o1;
            }
            if (lane == 0) {
                const int row = (b << 11) + i0 + wid * 8 + 2 * p;
                atomicMax(&g_best[row], pk0);
                atomicMax(&g_best[row + 1], pk1);
            }
        }
    }
}

// ---------------------------------------------------------------------------
// gather + one-hot write (one warp per output row)
// ---------------------------------------------------------------------------
__global__ void __launch_bounds__(256)
gather_onehot_kernel(const float* __restrict__ s2, float* __restrict__ out)
{
    const int w    = threadIdx.x >> 5;
    const int lane = threadIdx.x & 31;
    const int r    = blockIdx.x * 8 + w;     // 0 .. BB*T1C-1
    const int b    = r >> 11;
    const int i    = r & (T1C - 1);
    const int j    = 2047 - (int)(unsigned)(g_best[r] & 0xFFFFFFFFull);

    const float4* src = (const float4*)(s2 + ((size_t)b * T2C + (size_t)j) * DD);
    float4*       dst = (float4*)(out + (size_t)r * DD);
    dst[lane]      = src[lane];
    dst[lane + 32] = src[lane + 32];

    if (lane == 0)
        out[(size_t)BB * T1C * DD + (size_t)b * T1C * T2C +
            (size_t)i * T2C + j] = 1.0f;
}

// ---------------------------------------------------------------------------
// host
// ---------------------------------------------------------------------------
extern "C" void kernel_launch(void* const* d_in, const int* in_sizes, int n_in,
                              void* d_out, int out_size)
{
    (void)in_sizes; (void)n_in; (void)out_size;
    const float* s1 = (const float*)d_in[0];
    const float* s2 = (const float*)d_in[1];
    float* out = (float*)d_out;

    init_best_kernel<<<(BB * T1C) / 512, 512>>>();

    cudaFuncSetAttribute(gemm_argmax_kernel,
                         cudaFuncAttributeMaxDynamicSharedMemorySize,
                         SMEM_TOTAL);
    gemm_argmax_kernel<<<NCTA, 512, SMEM_TOTAL>>>(s1, s2, out);

    gather_onehot_kernel<<<(BB * T1C) / 8, 256>>>(s2, out);
}

// round 10
// speedup vs baseline: 1.0011x; 1.0005x over previous
#include <cuda_runtime.h>
#include <cstdint>
#include <cstddef>
#include <cfloat>

// Problem shape
#define BB   8
#define T1C  2048
#define T2C  2048
#define DD   256

// Work decomposition: 2048 units = 8 b x 16 i-tiles(128) x 16 j-tiles(128)
#define UNITS  2048
#define NCTA   148

// smem layout
#define BMP  132                      // A row pad (floats)
#define BNU  129                      // B row stride (u64, odd -> 2-way STS only)
#define SM_BS (256 * BMP * 4)         // 135168
#define SMEM_TOTAL (SM_BS + 2 * 32 * BNU * 8)   // 135168 + 66048 = 201216

typedef unsigned long long ull;

__device__ ull g_best[BB * T1C];      // (enc(score)<<32) | (2047-j)

// ---------------------------------------------------------------------------
static __device__ __forceinline__ ull pk2(float lo, float hi) {
    ull r;
    asm("mov.b64 %0, {%1, %2};" : "=l"(r) : "f"(lo), "f"(hi));
    return r;
}
static __device__ __forceinline__ ull fma2(ull a, ull b, ull c) {
    ull d;
    asm("fma.rn.f32x2 %0, %1, %2, %3;" : "=l"(d) : "l"(a), "l"(b), "l"(c));
    return d;
}
static __device__ __forceinline__ void upk2(ull v, float& lo, float& hi) {
    asm("mov.b64 {%0, %1}, %2;" : "=f"(lo), "=f"(hi) : "l"(v));
}
// order-preserving float->uint encoding
static __device__ __forceinline__ unsigned enc(float x) {
    unsigned u = __float_as_uint(x);
    return (u & 0x80000000u) ? ~u : (u | 0x80000000u);
}

// ---------------------------------------------------------------------------
// init: reset the per-row best records (graph-replay safe)
// ---------------------------------------------------------------------------
__global__ void __launch_bounds__(512)
init_best_kernel()
{
    g_best[blockIdx.x * 512 + threadIdx.x] = 0ull;   // < enc of any real score
}

// ---------------------------------------------------------------------------
// Persistent fp32 GEMM + argmax. 148 CTAs x 512 threads, 1 CTA/SM.
// Per unit: full-K (256) dot of a 128x128 (i,j) tile; FFMA2 packed over
// i-pairs; B operands pre-duplicated as (b,b) u64 in smem so the inner loop
// is loads + FFMA2 only. Microtile: 8 i (4 u64 pairs) x 4 j per thread,
// j strided by 32 so B loads are conflict-free LDS.64.
// ---------------------------------------------------------------------------
__global__ void __launch_bounds__(512, 1)
gemm_argmax_kernel(const float* __restrict__ s1, const float* __restrict__ s2,
                   float* __restrict__ out)
{
    extern __shared__ __align__(16) char smem[];
    float* As = (float*)smem;                       // As[k][i], k-major
    ull*   Bs = (ull*)(smem + SM_BS);               // Bs[2][32][BNU] dup pairs

    const int tid  = threadIdx.x;
    const int wid  = tid >> 5, lane = tid & 31;
    const int c    = blockIdx.x;

    // ---- zero the one-hot output region (replaces cudaMemset; overlaps)
    {
        const float4 z = make_float4(0.f, 0.f, 0.f, 0.f);
        float4* oz = (float4*)(out + (size_t)BB * T1C * DD);
        const size_t tot = (size_t)BB * T1C * T2C / 4;
        for (size_t p = (size_t)c * 512 + tid; p < tot; p += (size_t)NCTA * 512)
            oz[p] = z;
    }

    const int u0 = (c * UNITS) / NCTA;
    const int u1 = ((c + 1) * UNITS) / NCTA;
    int curA = -1;

    #pragma unroll 1
    for (int u = u0; u < u1; u++) {
        const int b  = u >> 8;
        const int it = (u >> 4) & 15;
        const int jt = u & 15;
        const int i0 = it * 128, j0 = jt * 128;
        const float* s1b = s1 + ((size_t)(b << 11) + i0) * DD;
        const float* s2b = s2 + ((size_t)(b << 11) + j0) * DD;

        // ---- (re)stage A tile when (b, i-tile) changes (~2x per CTA)
        if ((u >> 4) != curA) {
            curA = u >> 4;
            __syncthreads();              // prior unit's As readers done
            #pragma unroll
            for (int r = 0; r < 16; r++) {
                int f = tid + 512 * r;
                int i = f >> 6, kq = f & 63;
                float4 v = ((const float4*)s1b)[(size_t)i * 64 + kq];
                int k = kq * 4;
                As[(k + 0) * BMP + i] = v.x;
                As[(k + 1) * BMP + i] = v.y;
                As[(k + 2) * BMP + i] = v.z;
                As[(k + 3) * BMP + i] = v.w;
            }
        }

        // ---- stage B chunk 0 (k 0..31) into buffer 0, duplicated pairs
        float4 rB[2];
        #pragma unroll
        for (int r = 0; r < 2; r++) {
            int f = tid + 512 * r;
            int j = f >> 3, kq = f & 7;
            rB[r] = ((const float4*)(s2b + (size_t)j * DD))[kq];
        }
        #pragma unroll
        for (int r = 0; r < 2; r++) {
            int f = tid + 512 * r;
            int j = f >> 3, k = (f & 7) * 4;
            Bs[(k + 0) * BNU + j] = pk2(rB[r].x, rB[r].x);
            Bs[(k + 1) * BNU + j] = pk2(rB[r].y, rB[r].y);
            Bs[(k + 2) * BNU + j] = pk2(rB[r].z, rB[r].z);
            Bs[(k + 3) * BNU + j] = pk2(rB[r].w, rB[r].w);
        }

        ull acc[4][4];
        #pragma unroll
        for (int p = 0; p < 4; p++)
            #pragma unroll
            for (int q = 0; q < 4; q++) acc[p][q] = 0ull;

        #pragma unroll 1
        for (int kc = 0; kc < 8; kc++) {
            __syncthreads();              // staged stores visible
            const int buf = kc & 1;

            if (kc < 7) {                 // prefetch next chunk from global
                const int kbase = (kc + 1) * 8;
                #pragma unroll
                for (int r = 0; r < 2; r++) {
                    int f = tid + 512 * r;
                    int j = f >> 3, kq = f & 7;
                    rB[r] = ((const float4*)(s2b + (size_t)j * DD))[kbase + kq];
                }
            }

            const float* Ab = As + (size_t)kc * 32 * BMP + wid * 8;
            const ull*   Bb = Bs + (size_t)buf * 32 * BNU + lane;
            #pragma unroll
            for (int kk = 0; kk < 32; kk++) {
                ulonglong2 a01 = *(const ulonglong2*)(Ab + kk * BMP);
                ulonglong2 a23 = *(const ulonglong2*)(Ab + kk * BMP + 4);
                ull b0 = Bb[kk * BNU];
                ull b1 = Bb[kk * BNU + 32];
                ull b2 = Bb[kk * BNU + 64];
                ull b3 = Bb[kk * BNU + 96];
                acc[0][0] = fma2(a01.x, b0, acc[0][0]);
                acc[1][0] = fma2(a01.y, b0, acc[1][0]);
                acc[2][0] = fma2(a23.x, b0, acc[2][0]);
                acc[3][0] = fma2(a23.y, b0, acc[3][0]);
                acc[0][1] = fma2(a01.x, b1, acc[0][1]);
                acc[1][1] = fma2(a01.y, b1, acc[1][1]);
                acc[2][1] = fma2(a23.x, b1, acc[2][1]);
                acc[3][1] = fma2(a23.y, b1, acc[3][1]);
                acc[0][2] = fma2(a01.x, b2, acc[0][2]);
                acc[1][2] = fma2(a01.y, b2, acc[1][2]);
                acc[2][2] = fma2(a23.x, b2, acc[2][2]);
                acc[3][2] = fma2(a23.y, b2, acc[3][2]);
                acc[0][3] = fma2(a01.x, b3, acc[0][3]);
                acc[1][3] = fma2(a01.y, b3, acc[1][3]);
                acc[2][3] = fma2(a23.x, b3, acc[2][3]);
                acc[3][3] = fma2(a23.y, b3, acc[3][3]);
            }

            // store prefetched chunk into the other buffer; its previous
            // readers finished before this iteration's top barrier, and its
            // next readers wait on the next iteration's top barrier.
            if (kc < 7) {
                ull* dst = Bs + (size_t)(buf ^ 1) * 32 * BNU;
                #pragma unroll
                for (int r = 0; r < 2; r++) {
                    int f = tid + 512 * r;
                    int j = f >> 3, k = (f & 7) * 4;
                    dst[(k + 0) * BNU + j] = pk2(rB[r].x, rB[r].x);
                    dst[(k + 1) * BNU + j] = pk2(rB[r].y, rB[r].y);
                    dst[(k + 2) * BNU + j] = pk2(rB[r].z, rB[r].z);
                    dst[(k + 3) * BNU + j] = pk2(rB[r].w, rB[r].w);
                }
            }
        }

        // ---- per-unit argmax fold: warp reduce, then one global atomic/row.
        // Thread's j values are j0 + lane + q*32: ascending in q, so strict
        // '>' keeps the smallest j within the thread; the packed u64 compare
        // (2047-j in low bits) breaks exact score ties toward smaller j
        // across threads/CTAs = numpy's first-max rule.
        #pragma unroll
        for (int p = 0; p < 4; p++) {
            float v0 = -FLT_MAX, v1 = -FLT_MAX;
            int   jA = 0, jB = 0;
            #pragma unroll
            for (int q = 0; q < 4; q++) {
                float lo, hi;
                upk2(acc[p][q], lo, hi);
                int jg = j0 + q * 32 + lane;
                if (lo > v0) { v0 = lo; jA = jg; }
                if (hi > v1) { v1 = hi; jB = jg; }
            }
            ull pk0 = ((ull)enc(v0) << 32) | (unsigned)(2047 - jA);
            ull pk1 = ((ull)enc(v1) << 32) | (unsigned)(2047 - jB);
            #pragma unroll
            for (int off = 16; off; off >>= 1) {
                ull o0 = __shfl_xor_sync(0xffffffffu, pk0, off);
                ull o1 = __shfl_xor_sync(0xffffffffu, pk1, off);
                if (o0 > pk0) pk0 = o0;
                if (o1 > pk1) pk1 = o1;
            }
            if (lane == 0) {
                const int row = (b << 11) + i0 + wid * 8 + 2 * p;
                atomicMax(&g_best[row], pk0);
                atomicMax(&g_best[row + 1], pk1);
            }
        }
    }
}

// ---------------------------------------------------------------------------
// gather + one-hot write (one warp per output row)
// ---------------------------------------------------------------------------
__global__ void __launch_bounds__(256)
gather_onehot_kernel(const float* __restrict__ s2, float* __restrict__ out)
{
    const int w    = threadIdx.x >> 5;
    const int lane = threadIdx.x & 31;
    const int r    = blockIdx.x * 8 + w;     // 0 .. BB*T1C-1
    const int b    = r >> 11;
    const int i    = r & (T1C - 1);
    const int j    = 2047 - (int)(unsigned)(g_best[r] & 0xFFFFFFFFull);

    const float4* src = (const float4*)(s2 + ((size_t)b * T2C + (size_t)j) * DD);
    float4*       dst = (float4*)(out + (size_t)r * DD);
    dst[lane]      = src[lane];
    dst[lane + 32] = src[lane + 32];

    if (lane == 0)
        out[(size_t)BB * T1C * DD + (size_t)b * T1C * T2C +
            (size_t)i * T2C + j] = 1.0f;
}

// ---------------------------------------------------------------------------
// host
// ---------------------------------------------------------------------------
extern "C" void kernel_launch(void* const* d_in, const int* in_sizes, int n_in,
                              void* d_out, int out_size)
{
    (void)in_sizes; (void)n_in; (void)out_size;
    const float* s1 = (const float*)d_in[0];
    const float* s2 = (const float*)d_in[1];
    float* out = (float*)d_out;

    init_best_kernel<<<(BB * T1C) / 512, 512>>>();

    cudaFuncSetAttribute(gemm_argmax_kernel,
                         cudaFuncAttributeMaxDynamicSharedMemorySize,
                         SMEM_TOTAL);
    gemm_argmax_kernel<<<NCTA, 512, SMEM_TOTAL>>>(s1, s2, out);

    gather_onehot_kernel<<<(BB * T1C) / 8, 256>>>(s2, out);
}